// round 12
// baseline (speedup 1.0000x reference)
#include <cuda_runtime.h>
#include <cuda_bf16.h>
#include <cstdint>

#define NN 50000
#define CC 128
#define EE 600000

// Scratch (device globals; no cudaMalloc allowed)
__device__ float g_x1[NN * CC];
__device__ float g_x2[NN * CC];
__device__ int   g_cnt[NN];
__device__ int   g_rs[NN];
__device__ int   g_cur[NN];
__device__ int   g_csr[EE];
__device__ int   g_part[128];
// Pre-transposed bf16 hi/lo weights: [gemm(3)][n(128)][k(256)]
__device__ __nv_bfloat16 g_wbh[3 * 128 * 256];
__device__ __nv_bfloat16 g_wbl[3 * 128 * 256];

// ---------------------------------------------------------------------------
__device__ __forceinline__ uint32_t smem_u32(const void* p) {
    uint32_t a;
    asm("{ .reg .u64 t; cvta.to.shared.u64 t, %1; cvt.u32.u64 %0, t; }" : "=r"(a) : "l"(p));
    return a;
}
__device__ __forceinline__ void ldsm_x4(uint32_t& r0, uint32_t& r1, uint32_t& r2, uint32_t& r3,
                                        uint32_t addr) {
    asm volatile("ldmatrix.sync.aligned.m8n8.x4.shared.b16 {%0,%1,%2,%3}, [%4];"
                 : "=r"(r0), "=r"(r1), "=r"(r2), "=r"(r3) : "r"(addr));
}
__device__ __forceinline__ void mma_bf16(float* d, const uint32_t* a, uint32_t b0, uint32_t b1) {
    asm volatile(
        "mma.sync.aligned.m16n8k16.row.col.f32.bf16.bf16.f32 "
        "{%0,%1,%2,%3}, {%4,%5,%6,%7}, {%8,%9}, {%0,%1,%2,%3};"
        : "+f"(d[0]), "+f"(d[1]), "+f"(d[2]), "+f"(d[3])
        : "r"(a[0]), "r"(a[1]), "r"(a[2]), "r"(a[3]), "r"(b0), "r"(b1));
}
__device__ __forceinline__ void cp_async16(uint32_t dst, const void* src) {
    asm volatile("cp.async.cg.shared.global [%0], [%1], 16;" :: "r"(dst), "l"(src) : "memory");
}

// ---------------------------------------------------------------------------
// CSR build
__global__ void count_kernel(const int* __restrict__ ei, int* __restrict__ cnt, int E) {
    int i = blockIdx.x * blockDim.x + threadIdx.x;
    if (i < E) atomicAdd(&cnt[ei[E + i]], 1);
}

__global__ void scan_local_kernel(const int* __restrict__ cnt, int* __restrict__ rs,
                                  int* __restrict__ part, int n) {
    __shared__ int sh[512];
    int t = threadIdx.x;
    int i = blockIdx.x * 512 + t;
    int v = (i < n) ? cnt[i] : 0;
    sh[t] = v;
    __syncthreads();
#pragma unroll
    for (int off = 1; off < 512; off <<= 1) {
        int add = (t >= off) ? sh[t - off] : 0;
        __syncthreads();
        sh[t] += add;
        __syncthreads();
    }
    if (i < n) rs[i] = sh[t] - v;
    if (t == 511) part[blockIdx.x] = sh[511];
}

__global__ void scan_part_kernel(int* __restrict__ part, int nb) {
    __shared__ int sh[128];
    int t = threadIdx.x;
    int v = (t < nb) ? part[t] : 0;
    sh[t] = v;
    __syncthreads();
#pragma unroll
    for (int off = 1; off < 128; off <<= 1) {
        int add = (t >= off) ? sh[t - off] : 0;
        __syncthreads();
        sh[t] += add;
        __syncthreads();
    }
    if (t < nb) part[t] = sh[t] - v;
}

__global__ void scan_add_kernel(int* __restrict__ rs, const int* __restrict__ part,
                                int* __restrict__ cur, int n) {
    int i = blockIdx.x * 512 + threadIdx.x;
    if (i < n) {
        int v = rs[i] + part[blockIdx.x];
        rs[i] = v;
        cur[i] = v;
    }
}

__global__ void fill_kernel(const int* __restrict__ ei, int* __restrict__ cur,
                            int* __restrict__ csr, int E) {
    int i = blockIdx.x * blockDim.x + threadIdx.x;
    if (i < E) {
        int slot = atomicAdd(&cur[ei[E + i]], 1);
        csr[slot] = ei[i];
    }
}

// ---------------------------------------------------------------------------
// Weight prep: W[k][n] (row-major, 2x 128x128 stacked in k) -> Wt[n][k] bf16 hi/lo
__global__ void prep_w_kernel(const float* w0l, const float* w0r,
                              const float* w1l, const float* w1r,
                              const float* w2l, const float* w2r,
                              __nv_bfloat16* wh, __nv_bfloat16* wl) {
    int gid = blockIdx.x * blockDim.x + threadIdx.x;   // [g][n][k]
    if (gid >= 3 * 128 * 256) return;
    int g = gid >> 15;
    int rem = gid & 32767;
    int n = rem >> 8;
    int k = rem & 255;
    const float* W;
    if (g == 0)      W = (k < 128) ? w0l : w0r;
    else if (g == 1) W = (k < 128) ? w1l : w1r;
    else             W = (k < 128) ? w2l : w2r;
    float v = W[(size_t)(k & 127) * CC + n];
    __nv_bfloat16 h = __float2bfloat16(v);
    __nv_bfloat16 l = __float2bfloat16(v - __bfloat162float(h));
    wh[gid] = h;
    wl[gid] = l;
}

// ---------------------------------------------------------------------------
// Fused bf16x3 tensor-core GEMM (mma.sync) with optional in-A-load mean-gather:
//   chunks 0-3: A rows = csr ? mean-gather of X0 neighbors : X0 rows directly
//   chunks 4-7: A rows = A1
// out[M,128] = act( [A0 | A1] (Mx256) @ Wt^T + bias )
// Static 40KB smem, single buffer, cp.async B in load phase (R11-measured layout).
#define ROW_B 80

__global__ __launch_bounds__(256, 2) void gemm_fused_kernel(
    const float* __restrict__ X0, const float* __restrict__ A1,
    const int* __restrict__ csr, const int* __restrict__ rs,
    const int* __restrict__ cnt,
    const __nv_bfloat16* __restrict__ wh, const __nv_bfloat16* __restrict__ wl,
    const float* __restrict__ bias,
    float* __restrict__ out, int M, int do_relu) {

    __shared__ __align__(16) char sA_hi[128 * ROW_B];
    __shared__ __align__(16) char sA_lo[128 * ROW_B];
    __shared__ __align__(16) char sB_hi[128 * ROW_B];
    __shared__ __align__(16) char sB_lo[128 * ROW_B];

    const int tid = threadIdx.x;
    const int lane = tid & 31;
    const int wid = tid >> 5;
    const int wm = (wid & 3) * 32;
    const int wn = (wid >> 2) * 64;
    const int row0 = blockIdx.x * 128;
    const bool doGather = (csr != nullptr);

    float acc[2][8][4] = {};

    const uint32_t aHi = smem_u32(sA_hi), aLo = smem_u32(sA_lo);
    const uint32_t bHi = smem_u32(sB_hi), bLo = smem_u32(sB_lo);

    const int a_mrow = ((lane >> 3) & 1) * 8 + (lane & 7);
    const int a_j = lane >> 4;
    const int b_nrow = (lane >> 4) * 8 + (lane & 7);
    const int b_j = (lane >> 3) & 1;

    // per-slot row geometry (row is independent of chunk)
    int rowArr[4], k4Arr[4];
    int myRs[4], myDeg[4];
#pragma unroll
    for (int i = 0; i < 4; i++) {
        int idx = tid + (i << 8);
        rowArr[i] = row0 + (idx >> 3);
        k4Arr[i] = idx & 7;
        if (doGather && rowArr[i] < M) {
            myRs[i] = __ldg(rs + rowArr[i]);
            myDeg[i] = __ldg(cnt + rowArr[i]);
        } else {
            myRs[i] = 0;
            myDeg[i] = 0;
        }
    }

    float4 vA[4];

    auto loadA = [&](int c) {
        const int koff = (c & 3) * 32;
        if (doGather && c < 4) {
            // mean-gather: sum 16B column slices of all neighbors
#pragma unroll
            for (int i = 0; i < 4; i++) {
                float4 s = make_float4(0.f, 0.f, 0.f, 0.f);
                const int deg = myDeg[i];
                if (rowArr[i] < M && deg > 0) {
                    const int* nb = csr + myRs[i];
                    const int k4 = k4Arr[i];
                    int j = 0;
                    for (; j + 4 <= deg; j += 4) {
                        int s0 = __ldg(nb + j), s1 = __ldg(nb + j + 1);
                        int s2 = __ldg(nb + j + 2), s3 = __ldg(nb + j + 3);
                        float4 v0 = __ldg((const float4*)(X0 + (size_t)s0 * CC + koff) + k4);
                        float4 v1 = __ldg((const float4*)(X0 + (size_t)s1 * CC + koff) + k4);
                        float4 v2 = __ldg((const float4*)(X0 + (size_t)s2 * CC + koff) + k4);
                        float4 v3 = __ldg((const float4*)(X0 + (size_t)s3 * CC + koff) + k4);
                        s.x += v0.x + v1.x + v2.x + v3.x;
                        s.y += v0.y + v1.y + v2.y + v3.y;
                        s.z += v0.z + v1.z + v2.z + v3.z;
                        s.w += v0.w + v1.w + v2.w + v3.w;
                    }
                    for (; j < deg; j++) {
                        int s0 = __ldg(nb + j);
                        float4 v0 = __ldg((const float4*)(X0 + (size_t)s0 * CC + koff) + k4);
                        s.x += v0.x; s.y += v0.y; s.z += v0.z; s.w += v0.w;
                    }
                    float inv = 1.0f / (float)deg;
                    s.x *= inv; s.y *= inv; s.z *= inv; s.w *= inv;
                }
                vA[i] = s;
            }
        } else {
            const float* SA = (c < 4) ? X0 : A1;
#pragma unroll
            for (int i = 0; i < 4; i++) {
                int row = rowArr[i];
                vA[i] = (row < M)
                    ? *(const float4*)(SA + (size_t)row * CC + koff + (k4Arr[i] << 2))
                    : make_float4(0.f, 0.f, 0.f, 0.f);
            }
        }
    };

    loadA(0);

    for (int c = 0; c < 8; c++) {
        // B chunk via cp.async (16B per op, 4 per thread)
#pragma unroll
        for (int i = 0; i < 2; i++) {
            int idx = tid + (i << 8);
            int n = idx >> 2, j = idx & 3;
            size_t srcOff = (size_t)n * 512 + (size_t)c * 64 + (size_t)j * 16;
            cp_async16(bHi + n * ROW_B + (j << 4), (const char*)wh + srcOff);
            cp_async16(bLo + n * ROW_B + (j << 4), (const char*)wl + srcOff);
        }
        asm volatile("cp.async.commit_group;" ::: "memory");

        // A chunk: split prefetched fp32 into bf16 hi/lo, STS
#pragma unroll
        for (int i = 0; i < 4; i++) {
            int idx = tid + (i << 8);
            int m = idx >> 3, k4 = idx & 7;
            float x0 = vA[i].x, x1 = vA[i].y, x2 = vA[i].z, x3 = vA[i].w;
            __nv_bfloat162 h01 = make_bfloat162(__float2bfloat16(x0), __float2bfloat16(x1));
            __nv_bfloat162 h23 = make_bfloat162(__float2bfloat16(x2), __float2bfloat16(x3));
            __nv_bfloat162 l01 = make_bfloat162(
                __float2bfloat16(x0 - __bfloat162float(h01.x)),
                __float2bfloat16(x1 - __bfloat162float(h01.y)));
            __nv_bfloat162 l23 = make_bfloat162(
                __float2bfloat16(x2 - __bfloat162float(h23.x)),
                __float2bfloat16(x3 - __bfloat162float(h23.y)));
            char* pd = sA_hi + m * ROW_B + (k4 << 3);
            *(__nv_bfloat162*)(pd + 0) = h01;
            *(__nv_bfloat162*)(pd + 4) = h23;
            char* pl = sA_lo + m * ROW_B + (k4 << 3);
            *(__nv_bfloat162*)(pl + 0) = l01;
            *(__nv_bfloat162*)(pl + 4) = l23;
        }

        // issue next chunk's A loads / gather early (hidden under this chunk's MMA)
        if (c < 7) loadA(c + 1);

        asm volatile("cp.async.wait_group 0;" ::: "memory");
        __syncthreads();

#pragma unroll
        for (int ks = 0; ks < 2; ks++) {
            uint32_t ah[8], al[8];
#pragma unroll
            for (int mi = 0; mi < 2; mi++) {
                uint32_t off = (uint32_t)((wm + mi * 16 + a_mrow) * ROW_B + ks * 32 + a_j * 16);
                ldsm_x4(ah[mi * 4 + 0], ah[mi * 4 + 1], ah[mi * 4 + 2], ah[mi * 4 + 3], aHi + off);
                ldsm_x4(al[mi * 4 + 0], al[mi * 4 + 1], al[mi * 4 + 2], al[mi * 4 + 3], aLo + off);
            }
#pragma unroll
            for (int bg = 0; bg < 4; bg++) {
                uint32_t off = (uint32_t)((wn + bg * 16 + b_nrow) * ROW_B + ks * 32 + b_j * 16);
                uint32_t bh0, bh1, bh2, bh3, bl0, bl1, bl2, bl3;
                ldsm_x4(bh0, bh1, bh2, bh3, bHi + off);
                ldsm_x4(bl0, bl1, bl2, bl3, bLo + off);
#pragma unroll
                for (int mi = 0; mi < 2; mi++) {
                    mma_bf16(acc[mi][bg * 2 + 0], ah + mi * 4, bh0, bh1);
                    mma_bf16(acc[mi][bg * 2 + 0], ah + mi * 4, bl0, bl1);
                    mma_bf16(acc[mi][bg * 2 + 0], al + mi * 4, bh0, bh1);
                    mma_bf16(acc[mi][bg * 2 + 1], ah + mi * 4, bh2, bh3);
                    mma_bf16(acc[mi][bg * 2 + 1], ah + mi * 4, bl2, bl3);
                    mma_bf16(acc[mi][bg * 2 + 1], al + mi * 4, bh2, bh3);
                }
            }
        }
        __syncthreads();
    }

    const int rbase = row0 + wm + (lane >> 2);
    const int cbase = wn + (lane & 3) * 2;
#pragma unroll
    for (int mi = 0; mi < 2; mi++) {
#pragma unroll
        for (int ni = 0; ni < 8; ni++) {
            int col = cbase + ni * 8;
            float b0 = __ldg(bias + col), b1 = __ldg(bias + col + 1);
            int r1 = rbase + mi * 16, r2 = r1 + 8;
            float v0 = acc[mi][ni][0] + b0, v1 = acc[mi][ni][1] + b1;
            float v2 = acc[mi][ni][2] + b0, v3 = acc[mi][ni][3] + b1;
            if (do_relu) {
                v0 = fmaxf(v0, 0.f); v1 = fmaxf(v1, 0.f);
                v2 = fmaxf(v2, 0.f); v3 = fmaxf(v3, 0.f);
            }
            if (r1 < M) *(float2*)(out + (size_t)r1 * CC + col) = make_float2(v0, v1);
            if (r2 < M) *(float2*)(out + (size_t)r2 * CC + col) = make_float2(v2, v3);
        }
    }
}

// ---------------------------------------------------------------------------
extern "C" void kernel_launch(void* const* d_in, const int* in_sizes, int n_in,
                              void* d_out, int out_size) {
    const float* x     = (const float*)d_in[0];
    const int*   ei    = (const int*)d_in[1];     // int32
    const float* W1_l  = (const float*)d_in[2];
    const float* b1_l  = (const float*)d_in[3];
    const float* W1_r  = (const float*)d_in[4];
    const float* W2_l  = (const float*)d_in[5];
    const float* b2_l  = (const float*)d_in[6];
    const float* W2_r  = (const float*)d_in[7];
    const float* W_lin = (const float*)d_in[8];
    const float* b_lin = (const float*)d_in[9];
    float* out = (float*)d_out;

    const int M = in_sizes[0] / CC;      // 50000
    const int E = in_sizes[1] / 2;       // 600000

    float *x1, *x2;
    int *cnt, *rs, *cur, *csr, *part;
    __nv_bfloat16 *wbh, *wbl;
    cudaGetSymbolAddress((void**)&x1, g_x1);
    cudaGetSymbolAddress((void**)&x2, g_x2);
    cudaGetSymbolAddress((void**)&cnt, g_cnt);
    cudaGetSymbolAddress((void**)&rs, g_rs);
    cudaGetSymbolAddress((void**)&cur, g_cur);
    cudaGetSymbolAddress((void**)&csr, g_csr);
    cudaGetSymbolAddress((void**)&part, g_part);
    cudaGetSymbolAddress((void**)&wbh, g_wbh);
    cudaGetSymbolAddress((void**)&wbl, g_wbl);

    const int TB = 256;
    const int gemmBlocks = (M + 127) / 128;
    const int edgeBlocks = (E + TB - 1) / TB;
    const int nScanBlk = (M + 511) / 512;

    // weight prep
    prep_w_kernel<<<384, TB>>>(W1_l, W1_r, W2_l, W2_r, W_lin, W_lin + 128 * CC, wbh, wbl);

    // CSR build (shared by both layers)
    cudaMemsetAsync(cnt, 0, (size_t)M * sizeof(int));
    count_kernel<<<edgeBlocks, TB>>>(ei, cnt, E);
    scan_local_kernel<<<nScanBlk, 512>>>(cnt, rs, part, M);
    scan_part_kernel<<<1, 128>>>(part, nScanBlk);
    scan_add_kernel<<<nScanBlk, 512>>>(rs, part, cur, M);
    fill_kernel<<<edgeBlocks, TB>>>(ei, cur, csr, E);

    // layer 1: fused mean-gather + GEMM
    gemm_fused_kernel<<<gemmBlocks, TB>>>(x, x, csr, rs, cnt,
                                          wbh, wbl, b1_l, x1, M, 1);

    // layer 2: fused mean-gather + GEMM
    gemm_fused_kernel<<<gemmBlocks, TB>>>(x1, x1, csr, rs, cnt,
                                          wbh + 32768, wbl + 32768, b2_l, x2, M, 1);

    // final linear: [x1 | x2] @ W_lin + b_lin (no gather, no relu)
    gemm_fused_kernel<<<gemmBlocks, TB>>>(x1, x2, nullptr, nullptr, nullptr,
                                          wbh + 65536, wbl + 65536, b_lin, out, M, 0);
}

// round 13
// speedup vs baseline: 1.7347x; 1.7347x over previous
#include <cuda_runtime.h>
#include <cuda_bf16.h>
#include <cstdint>

#define NN 50000
#define CC 128
#define EE 600000

// Scratch (device globals; no cudaMalloc allowed)
__device__ float g_x1[NN * CC];
__device__ float g_x2[NN * CC];
__device__ float g_yl[NN * CC];
__device__ float g_yr[NN * CC];
__device__ int   g_cnt[NN];
__device__ int   g_rs[NN];
__device__ int   g_cur[NN];
__device__ int   g_csr[EE];
__device__ int   g_part[128];
// Pre-transposed bf16 hi/lo weights: [gemm(3)][n(128)][k(256)]
__device__ __nv_bfloat16 g_wbh[3 * 128 * 256];
__device__ __nv_bfloat16 g_wbl[3 * 128 * 256];

// ---------------------------------------------------------------------------
__device__ __forceinline__ uint32_t smem_u32(const void* p) {
    uint32_t a;
    asm("{ .reg .u64 t; cvta.to.shared.u64 t, %1; cvt.u32.u64 %0, t; }" : "=r"(a) : "l"(p));
    return a;
}
__device__ __forceinline__ void ldsm_x4(uint32_t& r0, uint32_t& r1, uint32_t& r2, uint32_t& r3,
                                        uint32_t addr) {
    asm volatile("ldmatrix.sync.aligned.m8n8.x4.shared.b16 {%0,%1,%2,%3}, [%4];"
                 : "=r"(r0), "=r"(r1), "=r"(r2), "=r"(r3) : "r"(addr));
}
__device__ __forceinline__ void mma_bf16(float* d, const uint32_t* a, uint32_t b0, uint32_t b1) {
    asm volatile(
        "mma.sync.aligned.m16n8k16.row.col.f32.bf16.bf16.f32 "
        "{%0,%1,%2,%3}, {%4,%5,%6,%7}, {%8,%9}, {%0,%1,%2,%3};"
        : "+f"(d[0]), "+f"(d[1]), "+f"(d[2]), "+f"(d[3])
        : "r"(a[0]), "r"(a[1]), "r"(a[2]), "r"(a[3]), "r"(b0), "r"(b1));
}
__device__ __forceinline__ void cp_async16(uint32_t dst, const void* src) {
    asm volatile("cp.async.cg.shared.global [%0], [%1], 16;" :: "r"(dst), "l"(src) : "memory");
}

// ---------------------------------------------------------------------------
// CSR build
__global__ void count_kernel(const int* __restrict__ ei, int* __restrict__ cnt, int E) {
    int i = blockIdx.x * blockDim.x + threadIdx.x;
    if (i < E) atomicAdd(&cnt[ei[E + i]], 1);
}

__global__ void scan_local_kernel(const int* __restrict__ cnt, int* __restrict__ rs,
                                  int* __restrict__ part, int n) {
    __shared__ int sh[512];
    int t = threadIdx.x;
    int i = blockIdx.x * 512 + t;
    int v = (i < n) ? cnt[i] : 0;
    sh[t] = v;
    __syncthreads();
#pragma unroll
    for (int off = 1; off < 512; off <<= 1) {
        int add = (t >= off) ? sh[t - off] : 0;
        __syncthreads();
        sh[t] += add;
        __syncthreads();
    }
    if (i < n) rs[i] = sh[t] - v;
    if (t == 511) part[blockIdx.x] = sh[511];
}

// merged: every block re-scans the (<=128) partials in smem, then applies offset
__global__ void scan_add_kernel(int* __restrict__ rs, const int* __restrict__ part,
                                int* __restrict__ cur, int n, int nb) {
    __shared__ int sh[128];
    int t = threadIdx.x;
    if (t < 128) sh[t] = (t < nb) ? part[t] : 0;
    __syncthreads();
#pragma unroll
    for (int off = 1; off < 128; off <<= 1) {
        int add = (t >= off && t < 128) ? sh[t - off] : 0;
        __syncthreads();
        if (t < 128) sh[t] += add;
        __syncthreads();
    }
    int boff = (blockIdx.x > 0) ? sh[blockIdx.x - 1] : 0;
    int i = blockIdx.x * 512 + t;
    if (i < n) {
        int v = rs[i] + boff;
        rs[i] = v;
        cur[i] = v;
    }
}

__global__ void fill_kernel(const int* __restrict__ ei, int* __restrict__ cur,
                            int* __restrict__ csr, int E) {
    int i = blockIdx.x * blockDim.x + threadIdx.x;
    if (i < E) {
        int slot = atomicAdd(&cur[ei[E + i]], 1);
        csr[slot] = ei[i];
    }
}

// ---------------------------------------------------------------------------
// combine: x_out = relu(mean_agg(Y_l) + bias + Y_r), warp per row.
__global__ __launch_bounds__(256) void combine_kernel(
    const float* __restrict__ yl, const float* __restrict__ yr,
    const int* __restrict__ csr, const int* __restrict__ rs,
    const int* __restrict__ cnt, const float* __restrict__ bias,
    float* __restrict__ out, int N) {
    int w = (blockIdx.x * blockDim.x + threadIdx.x) >> 5;
    if (w >= N) return;
    const int lane = threadIdx.x & 31;
    const int start = rs[w];
    const int deg = cnt[w];
    const int* nb = csr + start;

    float4 acc = make_float4(0.f, 0.f, 0.f, 0.f);
    int j = 0;
    for (; j + 4 <= deg; j += 4) {
        int s0 = __ldg(nb + j), s1 = __ldg(nb + j + 1);
        int s2 = __ldg(nb + j + 2), s3 = __ldg(nb + j + 3);
        float4 v0 = __ldg((const float4*)(yl + (size_t)s0 * CC) + lane);
        float4 v1 = __ldg((const float4*)(yl + (size_t)s1 * CC) + lane);
        float4 v2 = __ldg((const float4*)(yl + (size_t)s2 * CC) + lane);
        float4 v3 = __ldg((const float4*)(yl + (size_t)s3 * CC) + lane);
        acc.x += v0.x + v1.x + v2.x + v3.x;
        acc.y += v0.y + v1.y + v2.y + v3.y;
        acc.z += v0.z + v1.z + v2.z + v3.z;
        acc.w += v0.w + v1.w + v2.w + v3.w;
    }
    for (; j < deg; j++) {
        int s0 = __ldg(nb + j);
        float4 v0 = __ldg((const float4*)(yl + (size_t)s0 * CC) + lane);
        acc.x += v0.x; acc.y += v0.y; acc.z += v0.z; acc.w += v0.w;
    }
    float inv = 1.0f / (float)(deg > 0 ? deg : 1);
    float4 b = __ldg((const float4*)bias + lane);
    float4 r = __ldg((const float4*)(yr + (size_t)w * CC) + lane);
    float4 o;
    o.x = fmaxf(acc.x * inv + b.x + r.x, 0.f);
    o.y = fmaxf(acc.y * inv + b.y + r.y, 0.f);
    o.z = fmaxf(acc.z * inv + b.z + r.z, 0.f);
    o.w = fmaxf(acc.w * inv + b.w + r.w, 0.f);
    ((float4*)(out + (size_t)w * CC))[lane] = o;
}

// ---------------------------------------------------------------------------
// Weight prep: W[k][n] (row-major, 2x 128x128 stacked in k) -> Wt[n][k] bf16 hi/lo
__global__ void prep_w_kernel(const float* w0l, const float* w0r,
                              const float* w1l, const float* w1r,
                              const float* w2l, const float* w2r,
                              __nv_bfloat16* wh, __nv_bfloat16* wl) {
    int gid = blockIdx.x * blockDim.x + threadIdx.x;   // [g][n][k]
    if (gid >= 3 * 128 * 256) return;
    int g = gid >> 15;
    int rem = gid & 32767;
    int n = rem >> 8;
    int k = rem & 255;
    const float* W;
    if (g == 0)      W = (k < 128) ? w0l : w0r;
    else if (g == 1) W = (k < 128) ? w1l : w1r;
    else             W = (k < 128) ? w2l : w2r;
    float v = W[(size_t)(k & 127) * CC + n];
    __nv_bfloat16 h = __float2bfloat16(v);
    __nv_bfloat16 l = __float2bfloat16(v - __bfloat162float(h));
    wh[gid] = h;
    wl[gid] = l;
}

// ---------------------------------------------------------------------------
#define ROW_B 80

// Transform GEMM: Y_half = X (Mx128) @ Wt[half]^T (128x128), half = blockIdx.y.
// 4 K-chunks; same pipeline/layout as the proven R11 kernel. No bias/relu.
__global__ __launch_bounds__(256, 2) void gemm_t_kernel(
    const float* __restrict__ X,
    const __nv_bfloat16* __restrict__ wh, const __nv_bfloat16* __restrict__ wl,
    float* __restrict__ yl, float* __restrict__ yr, int M) {

    __shared__ __align__(16) char sA_hi[128 * ROW_B];
    __shared__ __align__(16) char sA_lo[128 * ROW_B];
    __shared__ __align__(16) char sB_hi[128 * ROW_B];
    __shared__ __align__(16) char sB_lo[128 * ROW_B];

    const int tid = threadIdx.x;
    const int lane = tid & 31;
    const int wid = tid >> 5;
    const int wm = (wid & 3) * 32;
    const int wn = (wid >> 2) * 64;
    const int row0 = blockIdx.x * 128;
    const int half = blockIdx.y;
    float* out = half ? yr : yl;

    float acc[2][8][4] = {};

    const uint32_t aHi = smem_u32(sA_hi), aLo = smem_u32(sA_lo);
    const uint32_t bHi = smem_u32(sB_hi), bLo = smem_u32(sB_lo);

    const int a_mrow = ((lane >> 3) & 1) * 8 + (lane & 7);
    const int a_j = lane >> 4;
    const int b_nrow = (lane >> 4) * 8 + (lane & 7);
    const int b_j = (lane >> 3) & 1;

    float4 vA[4];

    auto loadA = [&](int c) {
        const int koff = c * 32;
#pragma unroll
        for (int i = 0; i < 4; i++) {
            int idx = tid + (i << 8);
            int m = idx >> 3, k4 = idx & 7;
            int row = row0 + m;
            vA[i] = (row < M) ? *(const float4*)(X + (size_t)row * CC + koff + (k4 << 2))
                              : make_float4(0.f, 0.f, 0.f, 0.f);
        }
    };

    loadA(0);

    for (int c = 0; c < 4; c++) {
        const int cb = half * 4 + c;     // chunk within the 256-k prep image
#pragma unroll
        for (int i = 0; i < 2; i++) {
            int idx = tid + (i << 8);
            int n = idx >> 2, j = idx & 3;
            size_t srcOff = (size_t)n * 512 + (size_t)cb * 64 + (size_t)j * 16;
            cp_async16(bHi + n * ROW_B + (j << 4), (const char*)wh + srcOff);
            cp_async16(bLo + n * ROW_B + (j << 4), (const char*)wl + srcOff);
        }
        asm volatile("cp.async.commit_group;" ::: "memory");

#pragma unroll
        for (int i = 0; i < 4; i++) {
            int idx = tid + (i << 8);
            int m = idx >> 3, k4 = idx & 7;
            float x0 = vA[i].x, x1 = vA[i].y, x2 = vA[i].z, x3 = vA[i].w;
            __nv_bfloat162 h01 = make_bfloat162(__float2bfloat16(x0), __float2bfloat16(x1));
            __nv_bfloat162 h23 = make_bfloat162(__float2bfloat16(x2), __float2bfloat16(x3));
            __nv_bfloat162 l01 = make_bfloat162(
                __float2bfloat16(x0 - __bfloat162float(h01.x)),
                __float2bfloat16(x1 - __bfloat162float(h01.y)));
            __nv_bfloat162 l23 = make_bfloat162(
                __float2bfloat16(x2 - __bfloat162float(h23.x)),
                __float2bfloat16(x3 - __bfloat162float(h23.y)));
            char* pd = sA_hi + m * ROW_B + (k4 << 3);
            *(__nv_bfloat162*)(pd + 0) = h01;
            *(__nv_bfloat162*)(pd + 4) = h23;
            char* pl = sA_lo + m * ROW_B + (k4 << 3);
            *(__nv_bfloat162*)(pl + 0) = l01;
            *(__nv_bfloat162*)(pl + 4) = l23;
        }

        if (c < 3) loadA(c + 1);

        asm volatile("cp.async.wait_group 0;" ::: "memory");
        __syncthreads();

#pragma unroll
        for (int ks = 0; ks < 2; ks++) {
            uint32_t ah[8], al[8];
#pragma unroll
            for (int mi = 0; mi < 2; mi++) {
                uint32_t off = (uint32_t)((wm + mi * 16 + a_mrow) * ROW_B + ks * 32 + a_j * 16);
                ldsm_x4(ah[mi * 4 + 0], ah[mi * 4 + 1], ah[mi * 4 + 2], ah[mi * 4 + 3], aHi + off);
                ldsm_x4(al[mi * 4 + 0], al[mi * 4 + 1], al[mi * 4 + 2], al[mi * 4 + 3], aLo + off);
            }
#pragma unroll
            for (int bg = 0; bg < 4; bg++) {
                uint32_t off = (uint32_t)((wn + bg * 16 + b_nrow) * ROW_B + ks * 32 + b_j * 16);
                uint32_t bh0, bh1, bh2, bh3, bl0, bl1, bl2, bl3;
                ldsm_x4(bh0, bh1, bh2, bh3, bHi + off);
                ldsm_x4(bl0, bl1, bl2, bl3, bLo + off);
#pragma unroll
                for (int mi = 0; mi < 2; mi++) {
                    mma_bf16(acc[mi][bg * 2 + 0], ah + mi * 4, bh0, bh1);
                    mma_bf16(acc[mi][bg * 2 + 0], ah + mi * 4, bl0, bl1);
                    mma_bf16(acc[mi][bg * 2 + 0], al + mi * 4, bh0, bh1);
                    mma_bf16(acc[mi][bg * 2 + 1], ah + mi * 4, bh2, bh3);
                    mma_bf16(acc[mi][bg * 2 + 1], ah + mi * 4, bl2, bl3);
                    mma_bf16(acc[mi][bg * 2 + 1], al + mi * 4, bh2, bh3);
                }
            }
        }
        __syncthreads();
    }

    const int rbase = row0 + wm + (lane >> 2);
    const int cbase = wn + (lane & 3) * 2;
#pragma unroll
    for (int mi = 0; mi < 2; mi++) {
#pragma unroll
        for (int ni = 0; ni < 8; ni++) {
            int col = cbase + ni * 8;
            int r1 = rbase + mi * 16, r2 = r1 + 8;
            if (r1 < M) *(float2*)(out + (size_t)r1 * CC + col) =
                make_float2(acc[mi][ni][0], acc[mi][ni][1]);
            if (r2 < M) *(float2*)(out + (size_t)r2 * CC + col) =
                make_float2(acc[mi][ni][2], acc[mi][ni][3]);
        }
    }
}

// ---------------------------------------------------------------------------
// Final GEMM (R11 kernel): out = [A0|A1] (Mx256) @ Wt^T + bias (no relu)
__global__ __launch_bounds__(256, 2) void gemm_mma_kernel(
    const float* __restrict__ A0, const float* __restrict__ A1,
    const __nv_bfloat16* __restrict__ wh, const __nv_bfloat16* __restrict__ wl,
    const float* __restrict__ bias,
    float* __restrict__ out, int M) {

    __shared__ __align__(16) char sA_hi[128 * ROW_B];
    __shared__ __align__(16) char sA_lo[128 * ROW_B];
    __shared__ __align__(16) char sB_hi[128 * ROW_B];
    __shared__ __align__(16) char sB_lo[128 * ROW_B];

    const int tid = threadIdx.x;
    const int lane = tid & 31;
    const int wid = tid >> 5;
    const int wm = (wid & 3) * 32;
    const int wn = (wid >> 2) * 64;
    const int row0 = blockIdx.x * 128;

    float acc[2][8][4] = {};

    const uint32_t aHi = smem_u32(sA_hi), aLo = smem_u32(sA_lo);
    const uint32_t bHi = smem_u32(sB_hi), bLo = smem_u32(sB_lo);

    const int a_mrow = ((lane >> 3) & 1) * 8 + (lane & 7);
    const int a_j = lane >> 4;
    const int b_nrow = (lane >> 4) * 8 + (lane & 7);
    const int b_j = (lane >> 3) & 1;

    float4 vA[4];

    auto loadA = [&](int c) {
        const float* SA = (c < 4) ? A0 : A1;
        const int koff = (c & 3) * 32;
#pragma unroll
        for (int i = 0; i < 4; i++) {
            int idx = tid + (i << 8);
            int m = idx >> 3, k4 = idx & 7;
            int row = row0 + m;
            vA[i] = (row < M) ? *(const float4*)(SA + (size_t)row * CC + koff + (k4 << 2))
                              : make_float4(0.f, 0.f, 0.f, 0.f);
        }
    };

    loadA(0);

    for (int c = 0; c < 8; c++) {
#pragma unroll
        for (int i = 0; i < 2; i++) {
            int idx = tid + (i << 8);
            int n = idx >> 2, j = idx & 3;
            size_t srcOff = (size_t)n * 512 + (size_t)c * 64 + (size_t)j * 16;
            cp_async16(bHi + n * ROW_B + (j << 4), (const char*)wh + srcOff);
            cp_async16(bLo + n * ROW_B + (j << 4), (const char*)wl + srcOff);
        }
        asm volatile("cp.async.commit_group;" ::: "memory");

#pragma unroll
        for (int i = 0; i < 4; i++) {
            int idx = tid + (i << 8);
            int m = idx >> 3, k4 = idx & 7;
            float x0 = vA[i].x, x1 = vA[i].y, x2 = vA[i].z, x3 = vA[i].w;
            __nv_bfloat162 h01 = make_bfloat162(__float2bfloat16(x0), __float2bfloat16(x1));
            __nv_bfloat162 h23 = make_bfloat162(__float2bfloat16(x2), __float2bfloat16(x3));
            __nv_bfloat162 l01 = make_bfloat162(
                __float2bfloat16(x0 - __bfloat162float(h01.x)),
                __float2bfloat16(x1 - __bfloat162float(h01.y)));
            __nv_bfloat162 l23 = make_bfloat162(
                __float2bfloat16(x2 - __bfloat162float(h23.x)),
                __float2bfloat16(x3 - __bfloat162float(h23.y)));
            char* pd = sA_hi + m * ROW_B + (k4 << 3);
            *(__nv_bfloat162*)(pd + 0) = h01;
            *(__nv_bfloat162*)(pd + 4) = h23;
            char* pl = sA_lo + m * ROW_B + (k4 << 3);
            *(__nv_bfloat162*)(pl + 0) = l01;
            *(__nv_bfloat162*)(pl + 4) = l23;
        }

        if (c < 7) loadA(c + 1);

        asm volatile("cp.async.wait_group 0;" ::: "memory");
        __syncthreads();

#pragma unroll
        for (int ks = 0; ks < 2; ks++) {
            uint32_t ah[8], al[8];
#pragma unroll
            for (int mi = 0; mi < 2; mi++) {
                uint32_t off = (uint32_t)((wm + mi * 16 + a_mrow) * ROW_B + ks * 32 + a_j * 16);
                ldsm_x4(ah[mi * 4 + 0], ah[mi * 4 + 1], ah[mi * 4 + 2], ah[mi * 4 + 3], aHi + off);
                ldsm_x4(al[mi * 4 + 0], al[mi * 4 + 1], al[mi * 4 + 2], al[mi * 4 + 3], aLo + off);
            }
#pragma unroll
            for (int bg = 0; bg < 4; bg++) {
                uint32_t off = (uint32_t)((wn + bg * 16 + b_nrow) * ROW_B + ks * 32 + b_j * 16);
                uint32_t bh0, bh1, bh2, bh3, bl0, bl1, bl2, bl3;
                ldsm_x4(bh0, bh1, bh2, bh3, bHi + off);
                ldsm_x4(bl0, bl1, bl2, bl3, bLo + off);
#pragma unroll
                for (int mi = 0; mi < 2; mi++) {
                    mma_bf16(acc[mi][bg * 2 + 0], ah + mi * 4, bh0, bh1);
                    mma_bf16(acc[mi][bg * 2 + 0], ah + mi * 4, bl0, bl1);
                    mma_bf16(acc[mi][bg * 2 + 0], al + mi * 4, bh0, bh1);
                    mma_bf16(acc[mi][bg * 2 + 1], ah + mi * 4, bh2, bh3);
                    mma_bf16(acc[mi][bg * 2 + 1], ah + mi * 4, bl2, bl3);
                    mma_bf16(acc[mi][bg * 2 + 1], al + mi * 4, bh2, bh3);
                }
            }
        }
        __syncthreads();
    }

    const int rbase = row0 + wm + (lane >> 2);
    const int cbase = wn + (lane & 3) * 2;
#pragma unroll
    for (int mi = 0; mi < 2; mi++) {
#pragma unroll
        for (int ni = 0; ni < 8; ni++) {
            int col = cbase + ni * 8;
            float b0 = __ldg(bias + col), b1 = __ldg(bias + col + 1);
            int r1 = rbase + mi * 16, r2 = r1 + 8;
            if (r1 < M) *(float2*)(out + (size_t)r1 * CC + col) =
                make_float2(acc[mi][ni][0] + b0, acc[mi][ni][1] + b1);
            if (r2 < M) *(float2*)(out + (size_t)r2 * CC + col) =
                make_float2(acc[mi][ni][2] + b0, acc[mi][ni][3] + b1);
        }
    }
}

// ---------------------------------------------------------------------------
extern "C" void kernel_launch(void* const* d_in, const int* in_sizes, int n_in,
                              void* d_out, int out_size) {
    const float* x     = (const float*)d_in[0];
    const int*   ei    = (const int*)d_in[1];     // int32
    const float* W1_l  = (const float*)d_in[2];
    const float* b1_l  = (const float*)d_in[3];
    const float* W1_r  = (const float*)d_in[4];
    const float* W2_l  = (const float*)d_in[5];
    const float* b2_l  = (const float*)d_in[6];
    const float* W2_r  = (const float*)d_in[7];
    const float* W_lin = (const float*)d_in[8];
    const float* b_lin = (const float*)d_in[9];
    float* out = (float*)d_out;

    const int M = in_sizes[0] / CC;      // 50000
    const int E = in_sizes[1] / 2;       // 600000

    float *x1, *x2, *yl, *yr;
    int *cnt, *rs, *cur, *csr, *part;
    __nv_bfloat16 *wbh, *wbl;
    cudaGetSymbolAddress((void**)&x1, g_x1);
    cudaGetSymbolAddress((void**)&x2, g_x2);
    cudaGetSymbolAddress((void**)&yl, g_yl);
    cudaGetSymbolAddress((void**)&yr, g_yr);
    cudaGetSymbolAddress((void**)&cnt, g_cnt);
    cudaGetSymbolAddress((void**)&rs, g_rs);
    cudaGetSymbolAddress((void**)&cur, g_cur);
    cudaGetSymbolAddress((void**)&csr, g_csr);
    cudaGetSymbolAddress((void**)&part, g_part);
    cudaGetSymbolAddress((void**)&wbh, g_wbh);
    cudaGetSymbolAddress((void**)&wbl, g_wbl);

    // side stream + events, created once on the (un-captured) correctness call
    static cudaStream_t s2 = nullptr;
    static cudaEvent_t evF = nullptr, evJ = nullptr;
    if (!s2) {
        cudaStreamCreateWithFlags(&s2, cudaStreamNonBlocking);
        cudaEventCreateWithFlags(&evF, cudaEventDisableTiming);
        cudaEventCreateWithFlags(&evJ, cudaEventDisableTiming);
    }

    const int TB = 256;
    const int gemmBlocks = (M + 127) / 128;          // 391
    const int combBlocks = (M * 32 + TB - 1) / TB;
    const int edgeBlocks = (E + TB - 1) / TB;
    const int nScanBlk = (M + 511) / 512;            // 98

    // ---- fork: CSR build on s2, prep + transform-GEMM1 on main ----
    cudaEventRecord(evF, 0);
    cudaStreamWaitEvent(s2, evF, 0);

    cudaMemsetAsync(cnt, 0, (size_t)M * sizeof(int), s2);
    count_kernel<<<edgeBlocks, TB, 0, s2>>>(ei, cnt, E);
    scan_local_kernel<<<nScanBlk, 512, 0, s2>>>(cnt, rs, part, M);
    scan_add_kernel<<<nScanBlk, 512, 0, s2>>>(rs, part, cur, M, nScanBlk);
    fill_kernel<<<edgeBlocks, TB, 0, s2>>>(ei, cur, csr, E);

    prep_w_kernel<<<384, TB>>>(W1_l, W1_r, W2_l, W2_r, W_lin, W_lin + 128 * CC, wbh, wbl);
    gemm_t_kernel<<<dim3(gemmBlocks, 2), TB>>>(x, wbh, wbl, yl, yr, M);   // Y1_l, Y1_r

    cudaEventRecord(evJ, s2);
    cudaStreamWaitEvent(0, evJ, 0);

    // ---- layer 1 combine: x1 = relu(mean_agg(Y1_l) + b1 + Y1_r) ----
    combine_kernel<<<combBlocks, TB>>>(yl, yr, csr, rs, cnt, b1_l, x1, M);

    // ---- layer 2 ----
    gemm_t_kernel<<<dim3(gemmBlocks, 2), TB>>>(x1, wbh + 32768, wbl + 32768, yl, yr, M);
    combine_kernel<<<combBlocks, TB>>>(yl, yr, csr, rs, cnt, b2_l, x2, M);

    // ---- final linear: [x1 | x2] @ W_lin + b_lin ----
    gemm_mma_kernel<<<gemmBlocks, TB>>>(x1, x2, wbh + 65536, wbl + 65536, b_lin, out, M);
}